// round 16
// baseline (speedup 1.0000x reference)
#include <cuda_runtime.h>

#define FULLMASK 0xffffffffu

// ---- packed f32x2 helpers (sm_103a FFMA2 path, PTX-only) -------------------
__device__ __forceinline__ unsigned long long pk2(float lo, float hi) {
  unsigned long long r;
  asm("mov.b64 %0, {%1, %2};" : "=l"(r) : "f"(lo), "f"(hi));
  return r;
}
__device__ __forceinline__ void upk2(unsigned long long v, float& lo, float& hi) {
  asm("mov.b64 {%0, %1}, %2;" : "=f"(lo), "=f"(hi) : "l"(v));
}
__device__ __forceinline__ unsigned long long fma2(unsigned long long a,
                                                   unsigned long long b,
                                                   unsigned long long c) {
  unsigned long long d;
  asm("fma.rn.f32x2 %0, %1, %2, %3;" : "=l"(d) : "l"(a), "l"(b), "l"(c));
  return d;
}

// P1 helper: one 256-float block = 16 rows x 16 cols, lane l holds row l.
//   hs = row-l sum (lane-local);  ls = col-l sum via butterfly reduce-scatter.
__device__ __forceinline__ void load_sums(const float* __restrict__ p, int l,
                                          float& hs, float& ls) {
  const float4* p4 = reinterpret_cast<const float4*>(p) + 4 * l;
  float4 x0 = p4[0], x1 = p4[1], x2 = p4[2], x3 = p4[3];
  float u[16] = {x0.x, x0.y, x0.z, x0.w, x1.x, x1.y, x1.z, x1.w,
                 x2.x, x2.y, x2.z, x2.w, x3.x, x3.y, x3.z, x3.w};
  hs = ((u[0] + u[1]) + (u[2] + u[3])) + ((u[4] + u[5]) + (u[6] + u[7])) +
       ((u[8] + u[9]) + (u[10] + u[11])) + ((u[12] + u[13]) + (u[14] + u[15]));

  bool b8 = (l & 8) != 0;
  float w[8];
#pragma unroll
  for (int k = 0; k < 8; k++) {
    float send = b8 ? u[k] : u[k + 8];
    float keep = b8 ? u[k + 8] : u[k];
    w[k] = keep + __shfl_xor_sync(FULLMASK, send, 8, 16);
  }
  bool b4 = (l & 4) != 0;
  float x[4];
#pragma unroll
  for (int k = 0; k < 4; k++) {
    float send = b4 ? w[k] : w[k + 4];
    float keep = b4 ? w[k + 4] : w[k];
    x[k] = keep + __shfl_xor_sync(FULLMASK, send, 4, 16);
  }
  bool b2 = (l & 2) != 0;
  float y[2];
#pragma unroll
  for (int k = 0; k < 2; k++) {
    float send = b2 ? x[k] : x[k + 2];
    float keep = b2 ? x[k + 2] : x[k];
    y[k] = keep + __shfl_xor_sync(FULLMASK, send, 2, 16);
  }
  bool b1 = (l & 1) != 0;
  float send = b1 ? y[0] : y[1];
  float keep = b1 ? y[1] : y[0];
  ls = keep + __shfl_xor_sync(FULLMASK, send, 1, 16);
}

// Warp = 4 rows = 32 nibble-adds, one per lane (P2/carry run full-width).
// Nibble-add id k: row-in-warp = k>>3, byte = (k>>1)&3, nib = k&1 (0=lo,1=hi).
// Vector stride 20 floats: 16B-aligned for LDS.128/STS.128, spreads banks.
__global__ __launch_bounds__(256, 4) void neural_alu_kernel(
    const float* __restrict__ A, const float* __restrict__ B,
    float* __restrict__ O, int nrows) {
  __shared__ __align__(16) float s_x[8][32][20];  // "a" nibble vecs; later el
  __shared__ __align__(16) float s_y[8][32][20];  // "b" nibble vecs
  __shared__ float s_c01[8][32][2];

  int tid  = threadIdx.x;
  int warp = tid >> 5;
  int lane = tid & 31;
  int h    = (lane >> 4) & 1;  // row within a row-pair
  int l    = lane & 15;
  int rowbase = (blockIdx.x * 8 + warp) * 4;

  // ---- P1: loads + row/col sums for 4 rows, publish 32 nibble vectors ------
#pragma unroll
  for (int rp = 0; rp < 2; rp++) {
    int row = rowbase + rp * 2 + h;
    if (row >= nrows) row = nrows - 1;  // never hit for exact grids
    const float* a = A + (size_t)row * 1024;
    const float* b = B + (size_t)row * 1024;
#pragma unroll
    for (int i = 0; i < 4; i++) {
      float ah, al, bl, bh;
      load_sums(a + i * 256, l, ah, al);
      load_sums(b + i * 256, l, bh, bl);
      int kL = rp * 16 + h * 8 + i * 2;
      s_x[warp][kL][l]     = al;
      s_x[warp][kL + 1][l] = ah;
      s_y[warp][kL][l]     = bl;
      s_y[warp][kL + 1][l] = bh;
    }
  }
  __syncwarp();

  // ---- P2: lane k = one complete nibble-add (all 32 lanes active) ----------
  int k = lane;
  float qsv[16];
  float inv_;
  {
    // -- operand "y": softmax numerators ey[16], Zy
    const float4* y4 = reinterpret_cast<const float4*>(s_y[warp][k]);
    float4 t0 = y4[0], t1 = y4[1], t2 = y4[2], t3 = y4[3];
    float ey[16] = {t0.x, t0.y, t0.z, t0.w, t1.x, t1.y, t1.z, t1.w,
                    t2.x, t2.y, t2.z, t2.w, t3.x, t3.y, t3.z, t3.w};
    float my = ey[0];
#pragma unroll
    for (int s = 1; s < 16; s++) my = fmaxf(my, ey[s]);
    float Zy = 0.f;
#pragma unroll
    for (int s = 0; s < 16; s++) { ey[s] = __expf(100.f * (ey[s] - my)); Zy += ey[s]; }

    // -- operand "x": max, then Zx + carry mass via suffix-sum identity
    //    C0*Z = sum_{A>=1} eA * SS_A,  SS_A = sum_{B>=16-A} ey[B]
    const float4* x4 = reinterpret_cast<const float4*>(s_x[warp][k]);
    float4 m0 = x4[0], m1 = x4[1], m2 = x4[2], m3 = x4[3];
    float xv[16] = {m0.x, m0.y, m0.z, m0.w, m1.x, m1.y, m1.z, m1.w,
                    m2.x, m2.y, m2.z, m2.w, m3.x, m3.y, m3.z, m3.w};
    float mx = xv[0];
#pragma unroll
    for (int s = 1; s < 16; s++) mx = fmaxf(mx, xv[s]);

    float Zx = __expf(100.f * (xv[0] - mx));
    float ss = 0.f, qhiT = 0.f;
#pragma unroll
    for (int Ai = 1; Ai < 16; Ai++) {
      float e = __expf(100.f * (xv[Ai] - mx));
      Zx += e;
      ss += ey[16 - Ai];
      qhiT = fmaf(e, ss, qhiT);
    }

    // -- packed rotation tables (even- and odd-aligned ey pairs)
    unsigned long long ep[8], op_[8];
#pragma unroll
    for (int j = 0; j < 8; j++) ep[j] = pk2(ey[2 * j], ey[2 * j + 1]);
#pragma unroll
    for (int j = 0; j < 8; j++) op_[j] = pk2(ey[(2 * j + 15) & 15], ey[2 * j]);

    // -- cyclic conv with FFMA2: qs2[t] = (q[2t], q[2t+1]) accumulators.
    //    x reloaded chunk-wise from smem; eA recomputed (keeps regs < 64).
    unsigned long long qs2[8] = {0, 0, 0, 0, 0, 0, 0, 0};
#pragma unroll
    for (int c = 0; c < 4; c++) {
      float4 xc = x4[c];
      float xr[4] = {xc.x, xc.y, xc.z, xc.w};
#pragma unroll
      for (int j = 0; j < 4; j++) {
        const int Ai = 4 * c + j;
        float e = __expf(100.f * (xr[j] - mx));
        unsigned long long e2 = pk2(e, e);
        if ((Ai & 1) == 0) {
          const int a = Ai >> 1;   // pair slot t uses ey[(2(t-a), 2(t-a)+1)]
#pragma unroll
          for (int t = 0; t < 8; t++) qs2[t] = fma2(e2, ep[(t - a) & 7], qs2[t]);
        } else {
          const int a = (Ai - 1) >> 1;  // slot t uses (ey[2(t-a)-1], ey[2(t-a)])
#pragma unroll
          for (int t = 0; t < 8; t++) qs2[t] = fma2(e2, op_[(t - a) & 7], qs2[t]);
        }
      }
    }
#pragma unroll
    for (int t = 0; t < 8; t++) upk2(qs2[t], qsv[2 * t], qsv[2 * t + 1]);

    inv_ = 1.0f / (Zx * Zy);
    float c0 = qhiT * inv_;                  // P(A+B > 15)
    float c1 = fmaf(qsv[15], inv_, c0);      // q[15] diagonal (no wrap at s=15)
    s_c01[warp][k][0] = c0;
    s_c01[warp][k][1] = c1;
  }
  __syncwarp();

  // ---- Carry chain: each lane replays its row's 8-step recurrence ----------
  // Then writes its output-softmax numerators. s_x is reused: lane k has
  // finished all reads of s_x[k]; cross-lane reads happen after __syncwarp.
  {
    int r = k >> 3;
    float pcs = 0.f, u1 = 0.f;
#pragma unroll
    for (int j = 0; j < 8; j++) {
      float pc = 1.f / (1.f + __expf(fmaf(-200.f, u1, 100.f)));
      float c0 = s_c01[warp][r * 8 + j][0];
      float c1 = s_c01[warp][r * 8 + j][1];
      if (j == (k & 7)) pcs = pc;
      u1 = fmaf(c1 - c0, pc, c0);
    }
    // sv[s] = (qs[s] + (qs[s-1]-qs[s])*pc) * inv ; e = exp(100*sv - 50)
    float Zl = 0.f;
#pragma unroll
    for (int s = 0; s < 16; s++) {
      float s0 = qsv[s];
      float s1 = qsv[(s + 15) & 15];
      float sv = fmaf(s1 - s0, pcs, s0) * inv_;
      float e  = __expf(fmaf(100.f, sv, -50.f));
      Zl += e;
      s_x[warp][k][s] = e;
    }
    s_x[warp][k][16] = 1.0f / Zl;
  }
  __syncwarp();

  // ---- P3: outer-product output for 4 rows, fully coalesced STG.128 --------
#pragma unroll
  for (int rp = 0; rp < 2; rp++) {
    int row = rowbase + rp * 2 + h;
    if (row >= nrows) row = nrows - 1;
    float* o = O + (size_t)row * 1024;
#pragma unroll
    for (int i = 0; i < 4; i++) {
      int kL = rp * 16 + h * 8 + i * 2, kH = kL + 1;
      // scale = (eh[l]/Zh) * (1/Zl); out[16l+m] = scale * el[m]
      float scale = (s_x[warp][kH][l] * s_x[warp][kH][16]) * s_x[warp][kL][16];
      const float4* e4 = reinterpret_cast<const float4*>(s_x[warp][kL]);
      float4 e0 = e4[0], e1 = e4[1], e2 = e4[2], e3 = e4[3];
      float4* op = reinterpret_cast<float4*>(o + i * 256) + 4 * l;
      op[0] = make_float4(scale * e0.x, scale * e0.y, scale * e0.z, scale * e0.w);
      op[1] = make_float4(scale * e1.x, scale * e1.y, scale * e1.z, scale * e1.w);
      op[2] = make_float4(scale * e2.x, scale * e2.y, scale * e2.z, scale * e2.w);
      op[3] = make_float4(scale * e3.x, scale * e3.y, scale * e3.z, scale * e3.w);
    }
  }
}

extern "C" void kernel_launch(void* const* d_in, const int* in_sizes, int n_in,
                              void* d_out, int out_size) {
  const float* a = (const float*)d_in[0];
  const float* b = (const float*)d_in[1];
  float*       o = (float*)d_out;
  int nrows = in_sizes[0] / 1024;            // (B,4,256) -> B rows of 1024
  int rows_per_block = 32;                    // 8 warps x 4 rows
  int blocks = (nrows + rows_per_block - 1) / rows_per_block;
  neural_alu_kernel<<<blocks, 256>>>(a, b, o, nrows);
}